// round 2
// baseline (speedup 1.0000x reference)
#include <cuda_runtime.h>
#include <cstdint>

#define TSEQ  512
#define BATCH 64
#define EMBD  512
#define HIDD  1024
#define G4    4096   // 4*HIDD
#define NBLK  128
#define NTHR  512
#define SMEM_BYTES 147456   // 2*(32KB W + 32KB X) + 16KB xp

// ---------------- scratch (static __device__ arrays; no allocation) ---------
__device__ float g_xp[(size_t)2 * TSEQ * G4 * BATCH];          // 1.07 GB
__device__ float g_hist[(size_t)2 * TSEQ * HIDD * BATCH];      // 268 MB
__device__ float g_hbuf[4 * HIDD * BATCH];                     // ping-pong h
__device__ float g_WT[(size_t)2 * HIDD * G4];                  // Whh^T [d][k][row]
__device__ unsigned g_cnt = 0;
__device__ volatile unsigned g_gen = 0;

// ---------------- f32x2 helpers --------------------------------------------
typedef unsigned long long u64;

__device__ __forceinline__ u64 dup2(float x) {
    u64 r; unsigned xi = __float_as_uint(x);
    asm("mov.b64 %0, {%1, %1};" : "=l"(r) : "r"(xi));
    return r;
}
__device__ __forceinline__ void fma2(u64 &d, u64 a, u64 b) {
    asm("fma.rn.f32x2 %0, %1, %2, %0;" : "+l"(d) : "l"(a), "l"(b));
}
__device__ __forceinline__ u64 add2(u64 a, u64 b) {
    u64 r; asm("add.rn.f32x2 %0, %1, %2;" : "=l"(r) : "l"(a), "l"(b));
    return r;
}
__device__ __forceinline__ float lo32(u64 v) { return __uint_as_float((unsigned)(v & 0xffffffffull)); }
__device__ __forceinline__ float hi32(u64 v) { return __uint_as_float((unsigned)(v >> 32)); }
__device__ __forceinline__ float sigmoidf_(float x) { return 1.0f / (1.0f + expf(-x)); }

// ---------------- cp.async helpers -----------------------------------------
__device__ __forceinline__ void cp16(void* dst, const void* src) {
    unsigned s = (unsigned)__cvta_generic_to_shared(dst);
    asm volatile("cp.async.cg.shared.global [%0], [%1], 16;" :: "r"(s), "l"(src));
}
__device__ __forceinline__ void cp_commit() { asm volatile("cp.async.commit_group;"); }
template<int N> __device__ __forceinline__ void cp_wait() {
    asm volatile("cp.async.wait_group %0;" :: "n"(N));
}

// ---------------- grid barrier ----------------------------------------------
__device__ __forceinline__ void grid_bar() {
    __syncthreads();
    if (threadIdx.x == 0) {
        unsigned my = g_gen;
        __threadfence();
        if (atomicAdd(&g_cnt, 1u) == NBLK - 1) {
            g_cnt = 0;
            __threadfence();
            g_gen = my + 1;
        } else {
            while (g_gen == my) { }
        }
    }
    __syncthreads();
}

// ---------------- Whh transpose: g_WT[d][k][row] = Whh_d[row][k] ------------
__global__ void transpose_kernel(const float* __restrict__ Wf,
                                 const float* __restrict__ Wb) {
    __shared__ float ts[32][33];
    const int d = blockIdx.z;
    const float* W = d ? Wb : Wf;
    const int k0 = blockIdx.x * 32, r0 = blockIdx.y * 32;
    const int tx = threadIdx.x, ty = threadIdx.y;   // 32 x 8
#pragma unroll
    for (int p = 0; p < 4; ++p)
        ts[ty + 8 * p][tx] = W[(size_t)(r0 + ty + 8 * p) * HIDD + k0 + tx];
    __syncthreads();
#pragma unroll
    for (int p = 0; p < 4; ++p)
        g_WT[((size_t)d * HIDD + k0 + ty + 8 * p) * G4 + r0 + tx] = ts[tx][ty + 8 * p];
}

// ---------------- x-projection (unchanged from R1 — known good) -------------
__global__ __launch_bounds__(256) void xproj_kernel(
    const int*   __restrict__ src,
    const float* __restrict__ emb,
    const float* __restrict__ Wih_f, const float* __restrict__ Wih_b,
    const float* __restrict__ bih_f, const float* __restrict__ bhh_f,
    const float* __restrict__ bih_b, const float* __restrict__ bhh_b)
{
    __shared__ float sW[64 * 36];
    __shared__ float sX[32 * 64];
    __shared__ int   sIdx[64];

    const int tid = threadIdx.x;
    const int gt  = blockIdx.x;
    const int t   = blockIdx.y;
    const int d   = blockIdx.z;

    const float* Wih = d ? Wih_b : Wih_f;
    const int t_src  = d ? (TSEQ - 1 - t) : t;

    if (tid < 64) sIdx[tid] = src[t_src * BATCH + tid];
    __syncthreads();

    const int wr = tid >> 2;
    const int wq = tid & 3;
    const float* wgp = Wih + (size_t)(gt * 64 + wr) * EMBD;
    const int xn = tid & 63;
    const int xq = tid >> 6;
    const int sidx = sIdx[xn];
    const float* erow = emb + (size_t)sidx * EMBD;
    const bool xzero = (sidx == 0);

    const int i = tid >> 4;
    const int j = tid & 15;

    u64 acc[4][2];
#pragma unroll
    for (int g = 0; g < 4; ++g) { acc[g][0] = 0ull; acc[g][1] = 0ull; }

    float4 wreg0, wreg1, xreg0, xreg1;
    wreg0 = *(const float4*)(wgp + wq * 4);
    wreg1 = *(const float4*)(wgp + wq * 4 + 16);
    if (xzero) { xreg0 = make_float4(0.f,0.f,0.f,0.f); xreg1 = xreg0; }
    else { xreg0 = *(const float4*)(erow + xq * 8); xreg1 = *(const float4*)(erow + xq * 8 + 4); }

    const int NC = EMBD / 32;
#pragma unroll 1
    for (int ch = 0; ch < NC; ++ch) {
        *(float4*)&sW[wr * 36 + wq * 4]      = wreg0;
        *(float4*)&sW[wr * 36 + wq * 4 + 16] = wreg1;
        {
            const float* x0 = (const float*)&xreg0;
            const float* x1 = (const float*)&xreg1;
#pragma unroll
            for (int s2 = 0; s2 < 4; ++s2) {
                sX[(xq * 8 + s2)     * 64 + xn] = x0[s2];
                sX[(xq * 8 + 4 + s2) * 64 + xn] = x1[s2];
            }
        }
        __syncthreads();
        if (ch + 1 < NC) {
            int k0 = (ch + 1) * 32;
            wreg0 = *(const float4*)(wgp + k0 + wq * 4);
            wreg1 = *(const float4*)(wgp + k0 + wq * 4 + 16);
            if (xzero) { xreg0 = make_float4(0.f,0.f,0.f,0.f); xreg1 = xreg0; }
            else { xreg0 = *(const float4*)(erow + k0 + xq * 8);
                   xreg1 = *(const float4*)(erow + k0 + xq * 8 + 4); }
        }
#pragma unroll
        for (int kb = 0; kb < 8; ++kb) {
            const int k4 = kb * 4;
            float4 w0 = *(const float4*)&sW[(i     ) * 36 + k4];
            float4 w1 = *(const float4*)&sW[(i + 16) * 36 + k4];
            float4 w2 = *(const float4*)&sW[(i + 32) * 36 + k4];
            float4 w3 = *(const float4*)&sW[(i + 48) * 36 + k4];
            const float* p0 = (const float*)&w0;
            const float* p1 = (const float*)&w1;
            const float* p2 = (const float*)&w2;
            const float* p3 = (const float*)&w3;
#pragma unroll
            for (int kk = 0; kk < 4; ++kk) {
                const u64* hx = (const u64*)&sX[(k4 + kk) * 64 + 4 * j];
                u64 h0 = hx[0], h1 = hx[1];
                u64 a;
                a = dup2(p0[kk]); fma2(acc[0][0], a, h0); fma2(acc[0][1], a, h1);
                a = dup2(p1[kk]); fma2(acc[1][0], a, h0); fma2(acc[1][1], a, h1);
                a = dup2(p2[kk]); fma2(acc[2][0], a, h0); fma2(acc[2][1], a, h1);
                a = dup2(p3[kk]); fma2(acc[3][0], a, h0); fma2(acc[3][1], a, h1);
            }
        }
        __syncthreads();
    }

    const float* bih = d ? bih_b : bih_f;
    const float* bhh = d ? bhh_b : bhh_f;
    float* xp = g_xp + (size_t)(d * TSEQ + t) * G4 * BATCH;
#pragma unroll
    for (int g = 0; g < 4; ++g) {
        int row = gt * 64 + i + g * 16;
        float bias = bih[row] + bhh[row];
        float4 o;
        o.x = lo32(acc[g][0]) + bias;
        o.y = hi32(acc[g][0]) + bias;
        o.z = lo32(acc[g][1]) + bias;
        o.w = hi32(acc[g][1]) + bias;
        *(float4*)&xp[(size_t)row * BATCH + 4 * j] = o;
    }
}

// ---------------- window staging (cp.async) ---------------------------------
__device__ __forceinline__ void stage_win(float* bufp, const float* WTd,
                                          const float* hprev, int win,
                                          int u0, int tid)
{
    // W: 64 rows x 128 k, WT layout [k][64 rows as 4 groups of 16]
#pragma unroll
    for (int s = 0; s < 4; ++s) {
        int c = tid * 4 + s;                 // 0..2047
        int k = c >> 4, rem = c & 15, v = rem >> 2, part = rem & 3;
        const float* src = WTd + (size_t)(win * 128 + k) * G4 + v * HIDD + u0 + part * 4;
        cp16(&bufp[k * 64 + v * 16 + part * 4], src);
    }
    float* bx = bufp + 8192;
#pragma unroll
    for (int s = 0; s < 4; ++s) {
        int c = tid * 4 + s;                 // 0..2047
        int k = c >> 4, part = c & 15;
        cp16(&bx[k * 64 + part * 4], hprev + (size_t)(win * 128 + k) * 64 + part * 4);
    }
}

// ---------------- persistent recurrence, both directions --------------------
// 128 blocks x 512 threads. block: dir = bid>>6, u0 = (bid&63)*16 (16 units x 4 gates = 64 rows)
// thread: ks = tid>>7 (K quarter), i = (tid&127)>>4 (8: row-pairs), j = tid&15 (4 batch)
__global__ __launch_bounds__(NTHR, 1) void persist_kernel()
{
    extern __shared__ float sm[];
    float* sXP = sm + 32768;              // 4096 floats
    u64*   red = (u64*)sm;                // reduction reuses buf0 (48KB)

    const int tid = threadIdx.x;
    const int bid = blockIdx.x;
    const int d   = bid >> 6;
    const int u0  = (bid & 63) * 16;
    const int ks  = tid >> 7;
    const int r   = tid & 127;
    const int i   = r >> 4;
    const int j   = r & 15;

    // zero h(-1) (parity-0 buffers, both dirs)
    {
        int z = bid * NTHR + tid;                      // 0..65535
        g_hbuf[z] = 0.0f;                              // d=0 parity 0
        g_hbuf[2 * HIDD * BATCH + z] = 0.0f;           // d=1 parity 0
    }
    float creg[2][4];
#pragma unroll
    for (int uu = 0; uu < 2; ++uu)
#pragma unroll
        for (int b = 0; b < 4; ++b) creg[uu][b] = 0.0f;

    grid_bar();

    const float* WTd = g_WT + (size_t)d * HIDD * G4;

    for (int t = 0; t < TSEQ; ++t) {
        const float* hprev = g_hbuf + (size_t)(d * 2 + (t & 1))       * (HIDD * BATCH);
        float*       hnext = g_hbuf + (size_t)(d * 2 + ((t + 1) & 1)) * (HIDD * BATCH);

        u64 acc[4][4];
#pragma unroll
        for (int v = 0; v < 4; ++v)
#pragma unroll
            for (int b = 0; b < 4; ++b) acc[v][b] = 0ull;

        // stage xp slice (64 rows x 64 b) + window 0
        const float* xpb = g_xp + (size_t)(d * TSEQ + t) * G4 * BATCH;
#pragma unroll
        for (int s = 0; s < 2; ++s) {
            int c = tid * 2 + s;               // 0..1023
            int v = c >> 8, rem = c & 255;
            cp16(&sXP[v * 1024 + rem * 4],
                 xpb + (size_t)v * HIDD * BATCH + u0 * BATCH + rem * 4);
        }
        stage_win(sm, WTd, hprev, 0, u0, tid);
        cp_commit();

#pragma unroll 1
        for (int win = 0; win < 8; ++win) {
            float* bw = sm + (win & 1) * 16384;
            float* bx = bw + 8192;
            if (win < 7) {
                stage_win(sm + ((win + 1) & 1) * 16384, WTd, hprev, win + 1, u0, tid);
                cp_commit();
                cp_wait<1>();
            } else {
                cp_wait<0>();
            }
            __syncthreads();
#pragma unroll 2
            for (int kb = 0; kb < 8; ++kb) {
                const int k0 = ks * 32 + kb * 4;
#pragma unroll
                for (int kk = 0; kk < 4; ++kk) {
                    float4 hb = *(const float4*)&bx[(k0 + kk) * 64 + 4 * j];
                    u64 h0 = dup2(hb.x), h1 = dup2(hb.y);
                    u64 h2 = dup2(hb.z), h3 = dup2(hb.w);
#pragma unroll
                    for (int v = 0; v < 4; ++v) {
                        u64 w = *(const u64*)&bw[(k0 + kk) * 64 + v * 16 + 2 * i];
                        fma2(acc[v][0], w, h0); fma2(acc[v][1], w, h1);
                        fma2(acc[v][2], w, h2); fma2(acc[v][3], w, h3);
                    }
                }
            }
            __syncthreads();
        }

        // K-split reduction through smem (buf0 area, free now)
        if (ks) {
            u64* dst = red + ((size_t)(ks - 1) * 128 + r) * 16;
#pragma unroll
            for (int v = 0; v < 4; ++v)
#pragma unroll
                for (int b = 0; b < 4; ++b) dst[v * 4 + b] = acc[v][b];
        }
        __syncthreads();

        if (ks == 0) {
#pragma unroll
            for (int v = 0; v < 4; ++v)
#pragma unroll
                for (int b = 0; b < 4; ++b) {
                    u64 s = acc[v][b];
                    s = add2(s, red[((size_t)0 * 128 + r) * 16 + v * 4 + b]);
                    s = add2(s, red[((size_t)1 * 128 + r) * 16 + v * 4 + b]);
                    s = add2(s, red[((size_t)2 * 128 + r) * 16 + v * 4 + b]);
                    acc[v][b] = s;
                }

            const int t_out = d ? (TSEQ - 1 - t) : t;
#pragma unroll
            for (int uu = 0; uu < 2; ++uu) {
                const int u = u0 + 2 * i + uu;
                float gt[4][4];
#pragma unroll
                for (int v = 0; v < 4; ++v) {
                    float4 xv = *(const float4*)&sXP[v * 1024 + (2 * i + uu) * 64 + 4 * j];
                    gt[v][0] = (uu ? hi32(acc[v][0]) : lo32(acc[v][0])) + xv.x;
                    gt[v][1] = (uu ? hi32(acc[v][1]) : lo32(acc[v][1])) + xv.y;
                    gt[v][2] = (uu ? hi32(acc[v][2]) : lo32(acc[v][2])) + xv.z;
                    gt[v][3] = (uu ? hi32(acc[v][3]) : lo32(acc[v][3])) + xv.w;
                }
                float4 hv;
                float* hl = (float*)&hv;
#pragma unroll
                for (int b = 0; b < 4; ++b) {
                    float ig = sigmoidf_(gt[0][b]);
                    float fg = sigmoidf_(gt[1][b]);
                    float gg = tanhf(gt[2][b]);
                    float og = sigmoidf_(gt[3][b]);
                    float cn = fg * creg[uu][b] + ig * gg;
                    creg[uu][b] = cn;
                    hl[b] = og * tanhf(cn);
                }
                *(float4*)&hnext[(size_t)u * BATCH + 4 * j] = hv;
                *(float4*)&g_hist[((size_t)(d * TSEQ + t_out) * HIDD + u) * BATCH + 4 * j] = hv;
            }
            __threadfence();
        }
        grid_bar();
    }
}

// ---------------- combine: out[b][t][h] = hf + hb ---------------------------
__global__ __launch_bounds__(256) void combine_kernel(float* __restrict__ out)
{
    __shared__ float s[128 * 65];
    const int uc  = blockIdx.x;
    const int t   = blockIdx.y;
    const int tid = threadIdx.x;
    const float* hf = g_hist + (size_t)t          * HIDD * BATCH;
    const float* hb = g_hist + (size_t)(TSEQ + t) * HIDD * BATCH;
    for (int x = tid; x < 128 * 64; x += 256) {
        int uu = x >> 6, b = x & 63;
        int u = uc * 128 + uu;
        s[uu * 65 + b] = hf[(size_t)u * BATCH + b] + hb[(size_t)u * BATCH + b];
    }
    __syncthreads();
    for (int x = tid; x < 128 * 64; x += 256) {
        int b = x >> 7, uu = x & 127;
        out[((size_t)b * TSEQ + t) * HIDD + uc * 128 + uu] = s[uu * 65 + b];
    }
}

// ---------------- launch -----------------------------------------------------
extern "C" void kernel_launch(void* const* d_in, const int* in_sizes, int n_in,
                              void* d_out, int out_size)
{
    const int*   src   = (const int*)  d_in[0];
    const float* emb   = (const float*)d_in[1];
    const float* Wih_f = (const float*)d_in[2];
    const float* Whh_f = (const float*)d_in[3];
    const float* bih_f = (const float*)d_in[4];
    const float* bhh_f = (const float*)d_in[5];
    const float* Wih_b = (const float*)d_in[6];
    const float* Whh_b = (const float*)d_in[7];
    const float* bih_b = (const float*)d_in[8];
    const float* bhh_b = (const float*)d_in[9];

    transpose_kernel<<<dim3(32, 128, 2), dim3(32, 8)>>>(Whh_f, Whh_b);
    xproj_kernel<<<dim3(64, 512, 2), 256>>>(src, emb, Wih_f, Wih_b,
                                            bih_f, bhh_f, bih_b, bhh_b);
    cudaFuncSetAttribute(persist_kernel,
                         cudaFuncAttributeMaxDynamicSharedMemorySize, SMEM_BYTES);
    persist_kernel<<<NBLK, NTHR, SMEM_BYTES>>>();
    combine_kernel<<<dim3(8, 512), 256>>>((float*)d_out);
}